// round 4
// baseline (speedup 1.0000x reference)
#include <cuda_runtime.h>
#include <math.h>
#include <stdint.h>

#define N_NODES 50000
#define N_EDGES 1600000
#define E_TOT   (N_EDGES + N_NODES)
#define HID     128
#define SLOPE   0.2f

// ------------------------- device scratch (no allocs allowed) ---------------
__device__ float g_XL[(size_t)N_NODES * HID];
__device__ float g_XR[(size_t)N_NODES * HID];
__device__ float g_H1[(size_t)N_NODES * HID];
__device__ int   g_DEG[N_NODES];
__device__ int   g_ROWPTR[N_NODES + 1];
__device__ int   g_CURSOR[N_NODES];
__device__ int   g_CSR[E_TOT];
__device__ int   g_is64;

// ------------------------- detect edge dtype + zero degrees ------------------
__global__ void k_detect_zero(const int* __restrict__ e) {
    int i = blockIdx.x * blockDim.x + threadIdx.x;
    if (i < N_NODES) g_DEG[i] = 0;
    if (blockIdx.x == 0) {
        __shared__ int s;
        if (threadIdx.x == 0) s = 0;
        __syncthreads();
        if (e[2 * threadIdx.x + 1] != 0) atomicOr(&s, 1);
        __syncthreads();
        if (threadIdx.x == 0) g_is64 = (s == 0) ? 1 : 0;
    }
}

__device__ __forceinline__ int edge_val(const void* e, int is64, int idx) {
    return is64 ? (int)((const long long*)e)[idx] : ((const int*)e)[idx];
}

// ------------------------- CSR build -----------------------------------------
__global__ void k_hist(const void* __restrict__ e) {
    int i = blockIdx.x * blockDim.x + threadIdx.x;
    if (i >= E_TOT) return;
    int is64 = g_is64;
    int d = (i < N_EDGES) ? edge_val(e, is64, N_EDGES + i) : (i - N_EDGES);
    atomicAdd(&g_DEG[d], 1);
}

// single-block warp-shuffle scan over all 50k degrees (replaces 3 kernels)
__global__ __launch_bounds__(1024) void k_scan() {
    __shared__ int wsum[32];
    __shared__ int carry_s;
    int tid = threadIdx.x, lane = tid & 31, w = tid >> 5;
    if (tid == 0) carry_s = 0;
    __syncthreads();
    for (int base = 0; base < N_NODES; base += 1024) {
        int i = base + tid;
        int v = (i < N_NODES) ? g_DEG[i] : 0;
        int inc = v;
        #pragma unroll
        for (int d = 1; d < 32; d <<= 1) {
            int t = __shfl_up_sync(0xFFFFFFFFu, inc, d);
            if (lane >= d) inc += t;
        }
        if (lane == 31) wsum[w] = inc;
        __syncthreads();
        if (w == 0) {
            int ws = wsum[lane];
            int wi = ws;
            #pragma unroll
            for (int d = 1; d < 32; d <<= 1) {
                int t = __shfl_up_sync(0xFFFFFFFFu, wi, d);
                if (lane >= d) wi += t;
            }
            wsum[lane] = wi;  // inclusive prefix of warp sums
        }
        __syncthreads();
        int woff = (w == 0) ? 0 : wsum[w - 1];
        int c = carry_s;
        int excl = inc - v + woff + c;
        if (i < N_NODES) { g_ROWPTR[i] = excl; g_CURSOR[i] = excl; }
        int tile_total = wsum[31];
        __syncthreads();
        if (tid == 0) carry_s = c + tile_total;
        __syncthreads();
    }
    if (tid == 0) g_ROWPTR[N_NODES] = E_TOT;
}

__global__ void k_scatter(const void* __restrict__ e) {
    int i = blockIdx.x * blockDim.x + threadIdx.x;
    if (i >= E_TOT) return;
    int is64 = g_is64;
    int s_, d_;
    if (i < N_EDGES) {
        s_ = edge_val(e, is64, i);
        d_ = edge_val(e, is64, N_EDGES + i);
    } else {
        s_ = d_ = i - N_EDGES;
    }
    int pos = atomicAdd(&g_CURSOR[d_], 1);
    g_CSR[pos] = s_;
}

// ------------------------- tf32 tensor-core dual GEMM ------------------------
// XL = A @ Wl and XR = A @ Wr as one [M x 256] GEMM (fp32 out).
// Block tile 128x256, 512 threads (16 warps 4Mx4N), warp tile 32x64.
#define AS_STRIDE 36
#define WS_STRIDE 264
#define GEMM_SMEM_BYTES ((128 * AS_STRIDE + 32 * WS_STRIDE) * 4)

__device__ __forceinline__ unsigned f2tf32(float x) {
    unsigned u;
    asm("cvt.rna.tf32.f32 %0, %1;" : "=r"(u) : "f"(x));
    return u;
}

__device__ __forceinline__ void mma_tf32(float4& d, const unsigned a[4], const unsigned b[2]) {
    asm volatile(
        "mma.sync.aligned.m16n8k8.row.col.f32.tf32.tf32.f32 "
        "{%0,%1,%2,%3}, {%4,%5,%6,%7}, {%8,%9}, {%0,%1,%2,%3};"
        : "+f"(d.x), "+f"(d.y), "+f"(d.z), "+f"(d.w)
        : "r"(a[0]), "r"(a[1]), "r"(a[2]), "r"(a[3]), "r"(b[0]), "r"(b[1]));
}

__global__ __launch_bounds__(512, 1) void k_gemm_tc(const float* __restrict__ A,
                                                    const float* __restrict__ Wl,
                                                    const float* __restrict__ Wr,
                                                    float* __restrict__ XL,
                                                    float* __restrict__ XR, int M) {
    extern __shared__ float sm[];
    float (*As)[AS_STRIDE] = (float(*)[AS_STRIDE])sm;
    float (*Ws)[WS_STRIDE] = (float(*)[WS_STRIDE])(sm + 128 * AS_STRIDE);

    int tid = threadIdx.x;
    int wid = tid >> 5, lane = tid & 31;
    int g = lane >> 2, t = lane & 3;
    int wm = wid & 3, wn = wid >> 2;
    int m0 = blockIdx.x * 128;

    float4 C[2][8];
    #pragma unroll
    for (int i = 0; i < 2; i++)
        #pragma unroll
        for (int j = 0; j < 8; j++) C[i][j] = make_float4(0.f, 0.f, 0.f, 0.f);

    for (int k0 = 0; k0 < 128; k0 += 32) {
        #pragma unroll
        for (int j = 0; j < 2; j++) {
            int f = tid + 512 * j;
            int row = f >> 3, col = (f & 7) * 4;
            float4 v = make_float4(0.f, 0.f, 0.f, 0.f);
            if (m0 + row < M)
                v = *(const float4*)(A + (size_t)(m0 + row) * 128 + k0 + col);
            As[row][col + 0] = __uint_as_float(f2tf32(v.x));
            As[row][col + 1] = __uint_as_float(f2tf32(v.y));
            As[row][col + 2] = __uint_as_float(f2tf32(v.z));
            As[row][col + 3] = __uint_as_float(f2tf32(v.w));
        }
        #pragma unroll
        for (int j = 0; j < 4; j++) {
            int f = tid + 512 * j;
            int row = f >> 6, col = (f & 63) * 4;
            const float* Wp = (col < 128) ? (Wl + (size_t)(k0 + row) * 128 + col)
                                          : (Wr + (size_t)(k0 + row) * 128 + (col - 128));
            float4 v = *(const float4*)Wp;
            Ws[row][col + 0] = __uint_as_float(f2tf32(v.x));
            Ws[row][col + 1] = __uint_as_float(f2tf32(v.y));
            Ws[row][col + 2] = __uint_as_float(f2tf32(v.z));
            Ws[row][col + 3] = __uint_as_float(f2tf32(v.w));
        }
        __syncthreads();

        #pragma unroll
        for (int ks = 0; ks < 32; ks += 8) {
            unsigned a[2][4], b[8][2];
            #pragma unroll
            for (int mt = 0; mt < 2; mt++) {
                int r = wm * 32 + mt * 16;
                a[mt][0] = __float_as_uint(As[r + g][ks + t]);
                a[mt][1] = __float_as_uint(As[r + g + 8][ks + t]);
                a[mt][2] = __float_as_uint(As[r + g][ks + t + 4]);
                a[mt][3] = __float_as_uint(As[r + g + 8][ks + t + 4]);
            }
            #pragma unroll
            for (int j = 0; j < 8; j++) {
                int n = wn * 64 + j * 8 + g;
                b[j][0] = __float_as_uint(Ws[ks + t][n]);
                b[j][1] = __float_as_uint(Ws[ks + t + 4][n]);
            }
            #pragma unroll
            for (int mt = 0; mt < 2; mt++)
                #pragma unroll
                for (int j = 0; j < 8; j++) mma_tf32(C[mt][j], a[mt], b[j]);
        }
        __syncthreads();
    }

    float* base = (wn < 2) ? XL : XR;
    int ncol0 = (wn & 1) * 64;
    #pragma unroll
    for (int mt = 0; mt < 2; mt++) {
        int r0 = m0 + wm * 32 + mt * 16 + g;
        #pragma unroll
        for (int j = 0; j < 8; j++) {
            int c = ncol0 + j * 8 + 2 * t;
            if (r0 < M)
                *(float2*)(base + (size_t)r0 * 128 + c) = make_float2(C[mt][j].x, C[mt][j].y);
            if (r0 + 8 < M)
                *(float2*)(base + (size_t)(r0 + 8) * 128 + c) = make_float2(C[mt][j].z, C[mt][j].w);
        }
    }
}

// ------------------------- GATv2 aggregation ---------------------------------
// Warp per dst node. No max-subtraction (logits bounded by glorot-scale
// weights; exp stays in fp32 range; softmax ratio identical). Unroll 8 for
// MLP=8 on the XL[src] gathers.
__device__ __forceinline__ float edge_logit(const float4& xs, const float4& xr,
                                            const float4& a4) {
    float4 mg = make_float4(xs.x + xr.x, xs.y + xr.y, xs.z + xr.z, xs.w + xr.w);
    float lx = fmaxf(mg.x, SLOPE * mg.x);
    float ly = fmaxf(mg.y, SLOPE * mg.y);
    float lz = fmaxf(mg.z, SLOPE * mg.z);
    float lw = fmaxf(mg.w, SLOPE * mg.w);
    return lx * a4.x + ly * a4.y + lz * a4.z + lw * a4.w;
}

__device__ __forceinline__ float head_reduce(float p) {
    p += __shfl_xor_sync(0xFFFFFFFFu, p, 1);
    p += __shfl_xor_sync(0xFFFFFFFFu, p, 2);
    p += __shfl_xor_sync(0xFFFFFFFFu, p, 4);
    return p;
}

__global__ __launch_bounds__(256) void k_agg(const float* __restrict__ XL,
                                             const float* __restrict__ XR,
                                             const float* __restrict__ att,
                                             const float* __restrict__ bias,
                                             float* __restrict__ out) {
    int warp = (blockIdx.x * blockDim.x + threadIdx.x) >> 5;
    int lane = threadIdx.x & 31;
    if (warp >= N_NODES) return;

    float4 a4 = __ldg((const float4*)att + lane);
    float4 xr = __ldg((const float4*)(XR + (size_t)warp * 128) + lane);
    int e0 = __ldg(&g_ROWPTR[warp]);
    int e1 = __ldg(&g_ROWPTR[warp + 1]);

    float s = 0.f;
    float4 acc = make_float4(0.f, 0.f, 0.f, 0.f);

    int e = e0;
    for (; e + 8 <= e1; e += 8) {
        float4 x[8];
        #pragma unroll
        for (int j = 0; j < 8; j++) {
            int src = __ldg(&g_CSR[e + j]);
            x[j] = __ldg((const float4*)(XL + (size_t)src * 128) + lane);
        }
        float w[8];
        #pragma unroll
        for (int j = 0; j < 8; j++)
            w[j] = __expf(head_reduce(edge_logit(x[j], xr, a4)));
        #pragma unroll
        for (int j = 0; j < 8; j++) {
            s += w[j];
            acc.x += w[j] * x[j].x;
            acc.y += w[j] * x[j].y;
            acc.z += w[j] * x[j].z;
            acc.w += w[j] * x[j].w;
        }
    }
    for (; e < e1; e++) {
        int src = __ldg(&g_CSR[e]);
        float4 xs = __ldg((const float4*)(XL + (size_t)src * 128) + lane);
        float w = __expf(head_reduce(edge_logit(xs, xr, a4)));
        s += w;
        acc.x += w * xs.x;
        acc.y += w * xs.y;
        acc.z += w * xs.z;
        acc.w += w * xs.w;
    }

    float inv = 1.f / (s + 1e-16f);
    float4 b4 = __ldg((const float4*)bias + lane);
    float4 o;
    o.x = fmaxf(acc.x * inv + b4.x, 0.f);
    o.y = fmaxf(acc.y * inv + b4.y, 0.f);
    o.z = fmaxf(acc.z * inv + b4.z, 0.f);
    o.w = fmaxf(acc.w * inv + b4.w, 0.f);
    *((float4*)(out + (size_t)warp * 128) + lane) = o;
}

// ------------------------- launch --------------------------------------------
extern "C" void kernel_launch(void* const* d_in, const int* in_sizes, int n_in,
                              void* d_out, int out_size) {
    const float* x    = (const float*)d_in[0];
    const void*  ei   = d_in[1];
    const float* W1l  = (const float*)d_in[2];
    const float* W1r  = (const float*)d_in[3];
    const float* att1 = (const float*)d_in[4];
    const float* b1   = (const float*)d_in[5];
    const float* W2l  = (const float*)d_in[6];
    const float* W2r  = (const float*)d_in[7];
    const float* att2 = (const float*)d_in[8];
    const float* b2   = (const float*)d_in[9];
    float* out = (float*)d_out;

    float *XL, *XR, *H1;
    cudaGetSymbolAddress((void**)&XL, g_XL);
    cudaGetSymbolAddress((void**)&XR, g_XR);
    cudaGetSymbolAddress((void**)&H1, g_H1);

    cudaFuncSetAttribute(k_gemm_tc, cudaFuncAttributeMaxDynamicSharedMemorySize,
                         GEMM_SMEM_BYTES);

    // side stream + events for fork-join overlap (host-side handles, created
    // once; work per call is identical and deterministic)
    static cudaStream_t s1 = nullptr;
    static cudaEvent_t evFork = nullptr, evG1 = nullptr;
    if (!s1) {
        cudaStreamCreateWithFlags(&s1, cudaStreamNonBlocking);
        cudaEventCreateWithFlags(&evFork, cudaEventDisableTiming);
        cudaEventCreateWithFlags(&evG1, cudaEventDisableTiming);
    }

    int gemm_grid = (N_NODES + 127) / 128;
    int agg_grid  = (N_NODES * 32 + 255) / 256;

    // fork: layer-1 GEMM on side stream, concurrent with CSR build
    cudaEventRecord(evFork, 0);
    cudaStreamWaitEvent(s1, evFork, 0);
    k_gemm_tc<<<gemm_grid, 512, GEMM_SMEM_BYTES, s1>>>(x, W1l, W1r, XL, XR, N_NODES);
    cudaEventRecord(evG1, s1);

    // CSR build on main stream
    k_detect_zero<<<(N_NODES + 255) / 256, 256>>>((const int*)ei);
    k_hist<<<(E_TOT + 255) / 256, 256>>>(ei);
    k_scan<<<1, 1024>>>();
    k_scatter<<<(E_TOT + 255) / 256, 256>>>(ei);

    // join
    cudaStreamWaitEvent(0, evG1, 0);

    // layer 1 aggregate
    k_agg<<<agg_grid, 256>>>(XL, XR, att1, b1, H1);

    // layer 2
    k_gemm_tc<<<gemm_grid, 512, GEMM_SMEM_BYTES>>>(H1, W2l, W2r, XL, XR, N_NODES);
    k_agg<<<agg_grid, 256>>>(XL, XR, att2, b2, out);
}

// round 5
// speedup vs baseline: 1.1230x; 1.1230x over previous
#include <cuda_runtime.h>
#include <math.h>
#include <stdint.h>

#define N_NODES 50000
#define N_EDGES 1600000
#define E_TOT   (N_EDGES + N_NODES)
#define HID     128
#define SLOPE   0.2f

// ------------------------- device scratch (no allocs allowed) ---------------
__device__ float g_XL[(size_t)N_NODES * HID];
__device__ float g_XR[(size_t)N_NODES * HID];
__device__ float g_H1[(size_t)N_NODES * HID];
__device__ int   g_DEG[N_NODES];
__device__ int   g_ROWPTR[N_NODES + 1];
__device__ int   g_CURSOR[N_NODES];
__device__ int   g_CSR[E_TOT];
__device__ int   g_PART[64];
__device__ int   g_is64;

// ------------------------- detect edge dtype + zero degrees ------------------
__global__ void k_detect_zero(const int* __restrict__ e) {
    int i = blockIdx.x * blockDim.x + threadIdx.x;
    if (i < N_NODES) g_DEG[i] = 0;
    if (blockIdx.x == 0) {
        __shared__ int s;
        if (threadIdx.x == 0) s = 0;
        __syncthreads();
        if (e[2 * threadIdx.x + 1] != 0) atomicOr(&s, 1);
        __syncthreads();
        if (threadIdx.x == 0) g_is64 = (s == 0) ? 1 : 0;
    }
}

__device__ __forceinline__ int edge_val(const void* e, int is64, int idx) {
    return is64 ? (int)((const long long*)e)[idx] : ((const int*)e)[idx];
}

// ------------------------- CSR build -----------------------------------------
__global__ void k_hist(const void* __restrict__ e) {
    int i = blockIdx.x * blockDim.x + threadIdx.x;
    if (i >= E_TOT) return;
    int is64 = g_is64;
    int d = (i < N_EDGES) ? edge_val(e, is64, N_EDGES + i) : (i - N_EDGES);
    atomicAdd(&g_DEG[d], 1);
}

__global__ void k_scan1() {
    __shared__ int s[1024];
    int i = blockIdx.x * 1024 + threadIdx.x;
    int v = (i < N_NODES) ? g_DEG[i] : 0;
    s[threadIdx.x] = v;
    __syncthreads();
    #pragma unroll
    for (int off = 1; off < 1024; off <<= 1) {
        int t = (threadIdx.x >= off) ? s[threadIdx.x - off] : 0;
        __syncthreads();
        s[threadIdx.x] += t;
        __syncthreads();
    }
    if (i < N_NODES) g_ROWPTR[i] = s[threadIdx.x] - v;  // block-local exclusive
    if (threadIdx.x == 1023) g_PART[blockIdx.x] = s[1023];
}

// fused: every block computes the prefix of the 49 block partials itself
__global__ void k_scan23(int nblk) {
    __shared__ int off_s;
    if (threadIdx.x < 64) {
        int v = (threadIdx.x < nblk) ? g_PART[threadIdx.x] : 0;
        // inclusive prefix over 64 lanes (2 warps) — do it with one warp only
        if (threadIdx.x < 32) {
            int a = v;
            #pragma unroll
            for (int d = 1; d < 32; d <<= 1) {
                int t = __shfl_up_sync(0xFFFFFFFFu, a, d);
                if ((threadIdx.x & 31) >= d) a += t;
            }
            // a = inclusive prefix of PART[0..31]
            if (threadIdx.x == (unsigned)min(31, (int)blockIdx.x))
                ;  // placeholder (no-op)
            // store exclusive prefix for blocks 0..31
            if (threadIdx.x < nblk) g_PART[threadIdx.x + 0] = a - v; // overwrite ok? need care
        }
    }
    __syncthreads();
    // NOTE: replaced below by simpler logic in k_scan23b
}

// simpler correct fused scan2+3: warp 0 of each block computes this block's
// offset by summing PART[0..blockIdx-1] (49 values, one warp pass).
__global__ __launch_bounds__(1024) void k_scan3f(int nblk) {
    __shared__ int off_s;
    if (threadIdx.x < 32) {
        int sum = 0;
        for (int b = threadIdx.x; b < nblk; b += 32)
            sum += (b < (int)blockIdx.x) ? g_PART[b] : 0;
        #pragma unroll
        for (int d = 16; d > 0; d >>= 1)
            sum += __shfl_down_sync(0xFFFFFFFFu, sum, d);
        if (threadIdx.x == 0) off_s = sum;
    }
    __syncthreads();
    int i = blockIdx.x * 1024 + threadIdx.x;
    if (i < N_NODES) {
        int r = g_ROWPTR[i] + off_s;
        g_ROWPTR[i] = r;
        g_CURSOR[i] = r;
    }
    if (i == 0) g_ROWPTR[N_NODES] = E_TOT;
}

__global__ void k_scatter(const void* __restrict__ e) {
    int i = blockIdx.x * blockDim.x + threadIdx.x;
    if (i >= E_TOT) return;
    int is64 = g_is64;
    int s_, d_;
    if (i < N_EDGES) {
        s_ = edge_val(e, is64, i);
        d_ = edge_val(e, is64, N_EDGES + i);
    } else {
        s_ = d_ = i - N_EDGES;
    }
    int pos = atomicAdd(&g_CURSOR[d_], 1);
    g_CSR[pos] = s_;
}

// ------------------------- tf32 tensor-core dual GEMM ------------------------
#define AS_STRIDE 36
#define WS_STRIDE 264
#define GEMM_SMEM_BYTES ((128 * AS_STRIDE + 32 * WS_STRIDE) * 4)

__device__ __forceinline__ unsigned f2tf32(float x) {
    unsigned u;
    asm("cvt.rna.tf32.f32 %0, %1;" : "=r"(u) : "f"(x));
    return u;
}

__device__ __forceinline__ void mma_tf32(float4& d, const unsigned a[4], const unsigned b[2]) {
    asm volatile(
        "mma.sync.aligned.m16n8k8.row.col.f32.tf32.tf32.f32 "
        "{%0,%1,%2,%3}, {%4,%5,%6,%7}, {%8,%9}, {%0,%1,%2,%3};"
        : "+f"(d.x), "+f"(d.y), "+f"(d.z), "+f"(d.w)
        : "r"(a[0]), "r"(a[1]), "r"(a[2]), "r"(a[3]), "r"(b[0]), "r"(b[1]));
}

__global__ __launch_bounds__(512, 1) void k_gemm_tc(const float* __restrict__ A,
                                                    const float* __restrict__ Wl,
                                                    const float* __restrict__ Wr,
                                                    float* __restrict__ XL,
                                                    float* __restrict__ XR, int M) {
    extern __shared__ float sm[];
    float (*As)[AS_STRIDE] = (float(*)[AS_STRIDE])sm;
    float (*Ws)[WS_STRIDE] = (float(*)[WS_STRIDE])(sm + 128 * AS_STRIDE);

    int tid = threadIdx.x;
    int wid = tid >> 5, lane = tid & 31;
    int g = lane >> 2, t = lane & 3;
    int wm = wid & 3, wn = wid >> 2;
    int m0 = blockIdx.x * 128;

    float4 C[2][8];
    #pragma unroll
    for (int i = 0; i < 2; i++)
        #pragma unroll
        for (int j = 0; j < 8; j++) C[i][j] = make_float4(0.f, 0.f, 0.f, 0.f);

    for (int k0 = 0; k0 < 128; k0 += 32) {
        #pragma unroll
        for (int j = 0; j < 2; j++) {
            int f = tid + 512 * j;
            int row = f >> 3, col = (f & 7) * 4;
            float4 v = make_float4(0.f, 0.f, 0.f, 0.f);
            if (m0 + row < M)
                v = *(const float4*)(A + (size_t)(m0 + row) * 128 + k0 + col);
            As[row][col + 0] = __uint_as_float(f2tf32(v.x));
            As[row][col + 1] = __uint_as_float(f2tf32(v.y));
            As[row][col + 2] = __uint_as_float(f2tf32(v.z));
            As[row][col + 3] = __uint_as_float(f2tf32(v.w));
        }
        #pragma unroll
        for (int j = 0; j < 4; j++) {
            int f = tid + 512 * j;
            int row = f >> 6, col = (f & 63) * 4;
            const float* Wp = (col < 128) ? (Wl + (size_t)(k0 + row) * 128 + col)
                                          : (Wr + (size_t)(k0 + row) * 128 + (col - 128));
            float4 v = *(const float4*)Wp;
            Ws[row][col + 0] = __uint_as_float(f2tf32(v.x));
            Ws[row][col + 1] = __uint_as_float(f2tf32(v.y));
            Ws[row][col + 2] = __uint_as_float(f2tf32(v.z));
            Ws[row][col + 3] = __uint_as_float(f2tf32(v.w));
        }
        __syncthreads();

        #pragma unroll
        for (int ks = 0; ks < 32; ks += 8) {
            unsigned a[2][4], b[8][2];
            #pragma unroll
            for (int mt = 0; mt < 2; mt++) {
                int r = wm * 32 + mt * 16;
                a[mt][0] = __float_as_uint(As[r + g][ks + t]);
                a[mt][1] = __float_as_uint(As[r + g + 8][ks + t]);
                a[mt][2] = __float_as_uint(As[r + g][ks + t + 4]);
                a[mt][3] = __float_as_uint(As[r + g + 8][ks + t + 4]);
            }
            #pragma unroll
            for (int j = 0; j < 8; j++) {
                int n = wn * 64 + j * 8 + g;
                b[j][0] = __float_as_uint(Ws[ks + t][n]);
                b[j][1] = __float_as_uint(Ws[ks + t + 4][n]);
            }
            #pragma unroll
            for (int mt = 0; mt < 2; mt++)
                #pragma unroll
                for (int j = 0; j < 8; j++) mma_tf32(C[mt][j], a[mt], b[j]);
        }
        __syncthreads();
    }

    float* base = (wn < 2) ? XL : XR;
    int ncol0 = (wn & 1) * 64;
    #pragma unroll
    for (int mt = 0; mt < 2; mt++) {
        int r0 = m0 + wm * 32 + mt * 16 + g;
        #pragma unroll
        for (int j = 0; j < 8; j++) {
            int c = ncol0 + j * 8 + 2 * t;
            if (r0 < M)
                *(float2*)(base + (size_t)r0 * 128 + c) = make_float2(C[mt][j].x, C[mt][j].y);
            if (r0 + 8 < M)
                *(float2*)(base + (size_t)(r0 + 8) * 128 + c) = make_float2(C[mt][j].z, C[mt][j].w);
        }
    }
}

// ------------------------- GATv2 aggregation ---------------------------------
// Warp per dst node, unroll 4, no online max (logits bounded -> exp safe).
// att·leaky(v) computed as (0.6a)·v + (0.4a)·|v|  (2 FMA/ch, |v| is operand mod)
__device__ __forceinline__ float edge_logit(const float4& xs, const float4& xr,
                                            const float4& a6, const float4& a4) {
    float vx = xs.x + xr.x, vy = xs.y + xr.y, vz = xs.z + xr.z, vw = xs.w + xr.w;
    float p;
    p = a6.x * vx + a4.x * fabsf(vx);
    p = fmaf(a6.y, vy, fmaf(a4.y, fabsf(vy), p));
    p = fmaf(a6.z, vz, fmaf(a4.z, fabsf(vz), p));
    p = fmaf(a6.w, vw, fmaf(a4.w, fabsf(vw), p));
    return p;
}

__device__ __forceinline__ float head_reduce(float p) {
    p += __shfl_xor_sync(0xFFFFFFFFu, p, 1);
    p += __shfl_xor_sync(0xFFFFFFFFu, p, 2);
    p += __shfl_xor_sync(0xFFFFFFFFu, p, 4);
    return p;
}

__global__ __launch_bounds__(256) void k_agg(const float* __restrict__ XL,
                                             const float* __restrict__ XR,
                                             const float* __restrict__ att,
                                             const float* __restrict__ bias,
                                             float* __restrict__ out) {
    int warp = (blockIdx.x * blockDim.x + threadIdx.x) >> 5;
    int lane = threadIdx.x & 31;
    if (warp >= N_NODES) return;

    float4 a = __ldg((const float4*)att + lane);
    float4 a6 = make_float4(0.6f * a.x, 0.6f * a.y, 0.6f * a.z, 0.6f * a.w);
    float4 a4 = make_float4(0.4f * a.x, 0.4f * a.y, 0.4f * a.z, 0.4f * a.w);
    float4 xr = __ldg((const float4*)(XR + (size_t)warp * 128) + lane);
    int e0 = __ldg(&g_ROWPTR[warp]);
    int e1 = __ldg(&g_ROWPTR[warp + 1]);

    float s = 0.f;
    float4 acc = make_float4(0.f, 0.f, 0.f, 0.f);

    int e = e0;
    for (; e + 4 <= e1; e += 4) {
        int s0 = __ldg(&g_CSR[e]), s1 = __ldg(&g_CSR[e + 1]);
        int s2 = __ldg(&g_CSR[e + 2]), s3 = __ldg(&g_CSR[e + 3]);
        float4 x0 = __ldg((const float4*)(XL + (size_t)s0 * 128) + lane);
        float4 x1 = __ldg((const float4*)(XL + (size_t)s1 * 128) + lane);
        float4 x2 = __ldg((const float4*)(XL + (size_t)s2 * 128) + lane);
        float4 x3 = __ldg((const float4*)(XL + (size_t)s3 * 128) + lane);

        float w0 = __expf(head_reduce(edge_logit(x0, xr, a6, a4)));
        float w1 = __expf(head_reduce(edge_logit(x1, xr, a6, a4)));
        float w2 = __expf(head_reduce(edge_logit(x2, xr, a6, a4)));
        float w3 = __expf(head_reduce(edge_logit(x3, xr, a6, a4)));

        s += w0 + w1 + w2 + w3;
        acc.x += w0 * x0.x + w1 * x1.x + w2 * x2.x + w3 * x3.x;
        acc.y += w0 * x0.y + w1 * x1.y + w2 * x2.y + w3 * x3.y;
        acc.z += w0 * x0.z + w1 * x1.z + w2 * x2.z + w3 * x3.z;
        acc.w += w0 * x0.w + w1 * x1.w + w2 * x2.w + w3 * x3.w;
    }
    for (; e < e1; e++) {
        int src = __ldg(&g_CSR[e]);
        float4 xs = __ldg((const float4*)(XL + (size_t)src * 128) + lane);
        float w = __expf(head_reduce(edge_logit(xs, xr, a6, a4)));
        s += w;
        acc.x += w * xs.x;
        acc.y += w * xs.y;
        acc.z += w * xs.z;
        acc.w += w * xs.w;
    }

    float inv = 1.f / (s + 1e-16f);
    float4 b4 = __ldg((const float4*)bias + lane);
    float4 o;
    o.x = fmaxf(acc.x * inv + b4.x, 0.f);
    o.y = fmaxf(acc.y * inv + b4.y, 0.f);
    o.z = fmaxf(acc.z * inv + b4.z, 0.f);
    o.w = fmaxf(acc.w * inv + b4.w, 0.f);
    *((float4*)(out + (size_t)warp * 128) + lane) = o;
}

// ------------------------- launch --------------------------------------------
extern "C" void kernel_launch(void* const* d_in, const int* in_sizes, int n_in,
                              void* d_out, int out_size) {
    const float* x    = (const float*)d_in[0];
    const void*  ei   = d_in[1];
    const float* W1l  = (const float*)d_in[2];
    const float* W1r  = (const float*)d_in[3];
    const float* att1 = (const float*)d_in[4];
    const float* b1   = (const float*)d_in[5];
    const float* W2l  = (const float*)d_in[6];
    const float* W2r  = (const float*)d_in[7];
    const float* att2 = (const float*)d_in[8];
    const float* b2   = (const float*)d_in[9];
    float* out = (float*)d_out;

    float *XL, *XR, *H1;
    cudaGetSymbolAddress((void**)&XL, g_XL);
    cudaGetSymbolAddress((void**)&XR, g_XR);
    cudaGetSymbolAddress((void**)&H1, g_H1);

    cudaFuncSetAttribute(k_gemm_tc, cudaFuncAttributeMaxDynamicSharedMemorySize,
                         GEMM_SMEM_BYTES);

    // CSR build
    k_detect_zero<<<(N_NODES + 255) / 256, 256>>>((const int*)ei);
    k_hist<<<(E_TOT + 255) / 256, 256>>>(ei);
    int nblk = (N_NODES + 1023) / 1024;
    k_scan1<<<nblk, 1024>>>();
    k_scan3f<<<nblk, 1024>>>(nblk);
    k_scatter<<<(E_TOT + 255) / 256, 256>>>(ei);

    int gemm_grid = (N_NODES + 127) / 128;
    int agg_grid  = (N_NODES * 32 + 255) / 256;

    // layer 1
    k_gemm_tc<<<gemm_grid, 512, GEMM_SMEM_BYTES>>>(x, W1l, W1r, XL, XR, N_NODES);
    k_agg<<<agg_grid, 256>>>(XL, XR, att1, b1, H1);

    // layer 2
    k_gemm_tc<<<gemm_grid, 512, GEMM_SMEM_BYTES>>>(H1, W2l, W2r, XL, XR, N_NODES);
    k_agg<<<agg_grid, 256>>>(XL, XR, att2, b2, out);
}

// round 6
// speedup vs baseline: 1.1852x; 1.0555x over previous
#include <cuda_runtime.h>
#include <math.h>
#include <stdint.h>

#define N_NODES 50000
#define N_EDGES 1600000
#define E_TOT   (N_EDGES + N_NODES)
#define HID     128
#define SLOPE   0.2f

// ------------------------- device scratch (no allocs allowed) ---------------
__device__ float g_XL[(size_t)N_NODES * HID];
__device__ float g_XR[(size_t)N_NODES * HID];
__device__ float g_H1[(size_t)N_NODES * HID];
__device__ int   g_DEG[N_NODES];        // zero-init; k_scan1 re-zeroes each pass
__device__ int   g_ROWPTR[N_NODES + 1];
__device__ int   g_CURSOR[N_NODES];
__device__ int   g_CSR[E_TOT];
__device__ int   g_PART[64];

// ------------------------- edge dtype helpers --------------------------------
// int64 edges: every odd 32-bit word is a zero high-half. int32: odd words are
// random node ids. Each block detects independently (256 words, fail-proof).
__device__ __forceinline__ int detect_is64(const void* e) {
    int flag = (((const int*)e)[2 * threadIdx.x + 1] != 0);
    return !__syncthreads_or(flag);
}

__device__ __forceinline__ int edge_val(const void* e, int is64, int idx) {
    return is64 ? (int)((const long long*)e)[idx] : ((const int*)e)[idx];
}

// ------------------------- CSR build -----------------------------------------
__global__ __launch_bounds__(256) void k_hist(const void* __restrict__ e) {
    int is64 = detect_is64(e);
    int i = blockIdx.x * 256 + threadIdx.x;
    if (i >= E_TOT) return;
    int d = (i < N_EDGES) ? edge_val(e, is64, N_EDGES + i) : (i - N_EDGES);
    atomicAdd(&g_DEG[d], 1);
}

__global__ __launch_bounds__(1024) void k_scan1() {
    __shared__ int s[1024];
    int i = blockIdx.x * 1024 + threadIdx.x;
    int v = (i < N_NODES) ? g_DEG[i] : 0;
    if (i < N_NODES) g_DEG[i] = 0;          // reset for next launch sequence
    s[threadIdx.x] = v;
    __syncthreads();
    #pragma unroll
    for (int off = 1; off < 1024; off <<= 1) {
        int t = (threadIdx.x >= off) ? s[threadIdx.x - off] : 0;
        __syncthreads();
        s[threadIdx.x] += t;
        __syncthreads();
    }
    if (i < N_NODES) g_ROWPTR[i] = s[threadIdx.x] - v;  // block-local exclusive
    if (threadIdx.x == 1023) g_PART[blockIdx.x] = s[1023];
}

// fused scan2+3: warp 0 of each block sums PART[0..blockIdx-1]
__global__ __launch_bounds__(1024) void k_scan3f(int nblk) {
    __shared__ int off_s;
    if (threadIdx.x < 32) {
        int sum = 0;
        for (int b = threadIdx.x; b < nblk; b += 32)
            sum += (b < (int)blockIdx.x) ? g_PART[b] : 0;
        #pragma unroll
        for (int d = 16; d > 0; d >>= 1)
            sum += __shfl_down_sync(0xFFFFFFFFu, sum, d);
        if (threadIdx.x == 0) off_s = sum;
    }
    __syncthreads();
    int i = blockIdx.x * 1024 + threadIdx.x;
    if (i < N_NODES) {
        int r = g_ROWPTR[i] + off_s;
        g_ROWPTR[i] = r;
        g_CURSOR[i] = r;
    }
    if (i == 0) g_ROWPTR[N_NODES] = E_TOT;
}

__global__ __launch_bounds__(256) void k_scatter(const void* __restrict__ e) {
    int is64 = detect_is64(e);
    int i = blockIdx.x * 256 + threadIdx.x;
    if (i >= E_TOT) return;
    int s_, d_;
    if (i < N_EDGES) {
        s_ = edge_val(e, is64, i);
        d_ = edge_val(e, is64, N_EDGES + i);
    } else {
        s_ = d_ = i - N_EDGES;
    }
    int pos = atomicAdd(&g_CURSOR[d_], 1);
    g_CSR[pos] = s_;
}

// ------------------------- tf32 tensor-core dual GEMM ------------------------
#define AS_STRIDE 36
#define WS_STRIDE 264
#define GEMM_SMEM_BYTES ((128 * AS_STRIDE + 32 * WS_STRIDE) * 4)

__device__ __forceinline__ unsigned f2tf32(float x) {
    unsigned u;
    asm("cvt.rna.tf32.f32 %0, %1;" : "=r"(u) : "f"(x));
    return u;
}

__device__ __forceinline__ void mma_tf32(float4& d, const unsigned a[4], const unsigned b[2]) {
    asm volatile(
        "mma.sync.aligned.m16n8k8.row.col.f32.tf32.tf32.f32 "
        "{%0,%1,%2,%3}, {%4,%5,%6,%7}, {%8,%9}, {%0,%1,%2,%3};"
        : "+f"(d.x), "+f"(d.y), "+f"(d.z), "+f"(d.w)
        : "r"(a[0]), "r"(a[1]), "r"(a[2]), "r"(a[3]), "r"(b[0]), "r"(b[1]));
}

__global__ __launch_bounds__(512, 1) void k_gemm_tc(const float* __restrict__ A,
                                                    const float* __restrict__ Wl,
                                                    const float* __restrict__ Wr,
                                                    float* __restrict__ XL,
                                                    float* __restrict__ XR, int M) {
    extern __shared__ float sm[];
    float (*As)[AS_STRIDE] = (float(*)[AS_STRIDE])sm;
    float (*Ws)[WS_STRIDE] = (float(*)[WS_STRIDE])(sm + 128 * AS_STRIDE);

    int tid = threadIdx.x;
    int wid = tid >> 5, lane = tid & 31;
    int g = lane >> 2, t = lane & 3;
    int wm = wid & 3, wn = wid >> 2;
    int m0 = blockIdx.x * 128;

    float4 C[2][8];
    #pragma unroll
    for (int i = 0; i < 2; i++)
        #pragma unroll
        for (int j = 0; j < 8; j++) C[i][j] = make_float4(0.f, 0.f, 0.f, 0.f);

    for (int k0 = 0; k0 < 128; k0 += 32) {
        #pragma unroll
        for (int j = 0; j < 2; j++) {
            int f = tid + 512 * j;
            int row = f >> 3, col = (f & 7) * 4;
            float4 v = make_float4(0.f, 0.f, 0.f, 0.f);
            if (m0 + row < M)
                v = *(const float4*)(A + (size_t)(m0 + row) * 128 + k0 + col);
            As[row][col + 0] = __uint_as_float(f2tf32(v.x));
            As[row][col + 1] = __uint_as_float(f2tf32(v.y));
            As[row][col + 2] = __uint_as_float(f2tf32(v.z));
            As[row][col + 3] = __uint_as_float(f2tf32(v.w));
        }
        #pragma unroll
        for (int j = 0; j < 4; j++) {
            int f = tid + 512 * j;
            int row = f >> 6, col = (f & 63) * 4;
            const float* Wp = (col < 128) ? (Wl + (size_t)(k0 + row) * 128 + col)
                                          : (Wr + (size_t)(k0 + row) * 128 + (col - 128));
            float4 v = *(const float4*)Wp;
            Ws[row][col + 0] = __uint_as_float(f2tf32(v.x));
            Ws[row][col + 1] = __uint_as_float(f2tf32(v.y));
            Ws[row][col + 2] = __uint_as_float(f2tf32(v.z));
            Ws[row][col + 3] = __uint_as_float(f2tf32(v.w));
        }
        __syncthreads();

        #pragma unroll
        for (int ks = 0; ks < 32; ks += 8) {
            unsigned a[2][4], b[8][2];
            #pragma unroll
            for (int mt = 0; mt < 2; mt++) {
                int r = wm * 32 + mt * 16;
                a[mt][0] = __float_as_uint(As[r + g][ks + t]);
                a[mt][1] = __float_as_uint(As[r + g + 8][ks + t]);
                a[mt][2] = __float_as_uint(As[r + g][ks + t + 4]);
                a[mt][3] = __float_as_uint(As[r + g + 8][ks + t + 4]);
            }
            #pragma unroll
            for (int j = 0; j < 8; j++) {
                int n = wn * 64 + j * 8 + g;
                b[j][0] = __float_as_uint(Ws[ks + t][n]);
                b[j][1] = __float_as_uint(Ws[ks + t + 4][n]);
            }
            #pragma unroll
            for (int mt = 0; mt < 2; mt++)
                #pragma unroll
                for (int j = 0; j < 8; j++) mma_tf32(C[mt][j], a[mt], b[j]);
        }
        __syncthreads();
    }

    float* base = (wn < 2) ? XL : XR;
    int ncol0 = (wn & 1) * 64;
    #pragma unroll
    for (int mt = 0; mt < 2; mt++) {
        int r0 = m0 + wm * 32 + mt * 16 + g;
        #pragma unroll
        for (int j = 0; j < 8; j++) {
            int c = ncol0 + j * 8 + 2 * t;
            if (r0 < M)
                *(float2*)(base + (size_t)r0 * 128 + c) = make_float2(C[mt][j].x, C[mt][j].y);
            if (r0 + 8 < M)
                *(float2*)(base + (size_t)(r0 + 8) * 128 + c) = make_float2(C[mt][j].z, C[mt][j].w);
        }
    }
}

// ------------------------- GATv2 aggregation ---------------------------------
// Warp per dst node, TWO edges in flight per warp: lanes 0-15 process even
// edges, lanes 16-31 odd edges; each lane owns 8 channels [8*hl, 8*hl+8).
// Head = 32 ch = 4 lanes -> 2 SHFLs reduce BOTH edges simultaneously; one
// __expf serves 2 edges. leaky: att·leaky(v) = (0.6a)·v + (0.4a)·|v|.
// No online max (logits bounded; softmax ratio identical).
__device__ __forceinline__ float logit8(const float4& xA, const float4& xB,
                                        const float4& xrA, const float4& xrB,
                                        const float4& a6A, const float4& a4A,
                                        const float4& a6B, const float4& a4B) {
    float vx = xA.x + xrA.x, vy = xA.y + xrA.y, vz = xA.z + xrA.z, vw = xA.w + xrA.w;
    float p = a6A.x * vx + a4A.x * fabsf(vx);
    p = fmaf(a6A.y, vy, fmaf(a4A.y, fabsf(vy), p));
    p = fmaf(a6A.z, vz, fmaf(a4A.z, fabsf(vz), p));
    p = fmaf(a6A.w, vw, fmaf(a4A.w, fabsf(vw), p));
    vx = xB.x + xrB.x; vy = xB.y + xrB.y; vz = xB.z + xrB.z; vw = xB.w + xrB.w;
    p = fmaf(a6B.x, vx, fmaf(a4B.x, fabsf(vx), p));
    p = fmaf(a6B.y, vy, fmaf(a4B.y, fabsf(vy), p));
    p = fmaf(a6B.z, vz, fmaf(a4B.z, fabsf(vz), p));
    p = fmaf(a6B.w, vw, fmaf(a4B.w, fabsf(vw), p));
    return p;
}

__global__ __launch_bounds__(256) void k_agg(const float* __restrict__ XL,
                                             const float* __restrict__ XR,
                                             const float* __restrict__ att,
                                             const float* __restrict__ bias,
                                             float* __restrict__ out) {
    int warp = (blockIdx.x * blockDim.x + threadIdx.x) >> 5;
    int lane = threadIdx.x & 31;
    if (warp >= N_NODES) return;
    int half = lane >> 4;        // 0: even edges, 1: odd edges
    int hl   = lane & 15;        // channels [8*hl, 8*hl+8)

    const float4* attp = (const float4*)att;
    float4 aA = __ldg(attp + 2 * hl), aB = __ldg(attp + 2 * hl + 1);
    float4 a6A = make_float4(0.6f * aA.x, 0.6f * aA.y, 0.6f * aA.z, 0.6f * aA.w);
    float4 a4A = make_float4(0.4f * aA.x, 0.4f * aA.y, 0.4f * aA.z, 0.4f * aA.w);
    float4 a6B = make_float4(0.6f * aB.x, 0.6f * aB.y, 0.6f * aB.z, 0.6f * aB.w);
    float4 a4B = make_float4(0.4f * aB.x, 0.4f * aB.y, 0.4f * aB.z, 0.4f * aB.w);

    const float4* xrp = (const float4*)(XR + (size_t)warp * 128);
    float4 xrA = __ldg(xrp + 2 * hl), xrB = __ldg(xrp + 2 * hl + 1);

    int e0 = __ldg(&g_ROWPTR[warp]);
    int e1 = __ldg(&g_ROWPTR[warp + 1]);

    float s = 0.f;
    float4 accA = make_float4(0.f, 0.f, 0.f, 0.f);
    float4 accB = make_float4(0.f, 0.f, 0.f, 0.f);

    int e = e0;
    // main loop: 4 edges per iteration (2 pair-steps in flight)
    for (; e + 4 <= e1; e += 4) {
        int s0 = __ldg(&g_CSR[e + half]);
        int s1 = __ldg(&g_CSR[e + 2 + half]);
        const float4* xp0 = (const float4*)(XL + (size_t)s0 * 128);
        const float4* xp1 = (const float4*)(XL + (size_t)s1 * 128);
        float4 x0A = __ldg(xp0 + 2 * hl), x0B = __ldg(xp0 + 2 * hl + 1);
        float4 x1A = __ldg(xp1 + 2 * hl), x1B = __ldg(xp1 + 2 * hl + 1);

        float p0 = logit8(x0A, x0B, xrA, xrB, a6A, a4A, a6B, a4B);
        float p1 = logit8(x1A, x1B, xrA, xrB, a6A, a4A, a6B, a4B);
        p0 += __shfl_xor_sync(0xFFFFFFFFu, p0, 1);
        p1 += __shfl_xor_sync(0xFFFFFFFFu, p1, 1);
        p0 += __shfl_xor_sync(0xFFFFFFFFu, p0, 2);
        p1 += __shfl_xor_sync(0xFFFFFFFFu, p1, 2);
        float w0 = __expf(p0), w1 = __expf(p1);

        s += w0 + w1;
        accA.x += w0 * x0A.x + w1 * x1A.x;
        accA.y += w0 * x0A.y + w1 * x1A.y;
        accA.z += w0 * x0A.z + w1 * x1A.z;
        accA.w += w0 * x0A.w + w1 * x1A.w;
        accB.x += w0 * x0B.x + w1 * x1B.x;
        accB.y += w0 * x0B.y + w1 * x1B.y;
        accB.z += w0 * x0B.z + w1 * x1B.z;
        accB.w += w0 * x0B.w + w1 * x1B.w;
    }
    // tail: 2 edges per step with validity masking
    for (; e < e1; e += 2) {
        int ei = e + half;
        bool valid = ei < e1;
        int src = __ldg(&g_CSR[valid ? ei : e]);
        const float4* xp = (const float4*)(XL + (size_t)src * 128);
        float4 xA = __ldg(xp + 2 * hl), xB = __ldg(xp + 2 * hl + 1);
        float p = logit8(xA, xB, xrA, xrB, a6A, a4A, a6B, a4B);
        p += __shfl_xor_sync(0xFFFFFFFFu, p, 1);
        p += __shfl_xor_sync(0xFFFFFFFFu, p, 2);
        float w = valid ? __expf(p) : 0.f;
        s += w;
        accA.x += w * xA.x; accA.y += w * xA.y;
        accA.z += w * xA.z; accA.w += w * xA.w;
        accB.x += w * xB.x; accB.y += w * xB.y;
        accB.z += w * xB.z; accB.w += w * xB.w;
    }

    // merge halves: s via xor (all lanes get total); accA down to lower half,
    // accB up to upper half.
    s += __shfl_xor_sync(0xFFFFFFFFu, s, 16);
    accA.x += __shfl_down_sync(0xFFFFFFFFu, accA.x, 16);
    accA.y += __shfl_down_sync(0xFFFFFFFFu, accA.y, 16);
    accA.z += __shfl_down_sync(0xFFFFFFFFu, accA.z, 16);
    accA.w += __shfl_down_sync(0xFFFFFFFFu, accA.w, 16);
    accB.x += __shfl_up_sync(0xFFFFFFFFu, accB.x, 16);
    accB.y += __shfl_up_sync(0xFFFFFFFFu, accB.y, 16);
    accB.z += __shfl_up_sync(0xFFFFFFFFu, accB.z, 16);
    accB.w += __shfl_up_sync(0xFFFFFFFFu, accB.w, 16);

    float inv = 1.f / (s + 1e-16f);
    float4 acc = half ? accB : accA;           // valid side per half
    float4 b4 = __ldg((const float4*)bias + 2 * hl + half);
    float4 o;
    o.x = fmaxf(acc.x * inv + b4.x, 0.f);
    o.y = fmaxf(acc.y * inv + b4.y, 0.f);
    o.z = fmaxf(acc.z * inv + b4.z, 0.f);
    o.w = fmaxf(acc.w * inv + b4.w, 0.f);
    *((float4*)(out + (size_t)warp * 128) + 2 * hl + half) = o;  // fully coalesced
}

// ------------------------- launch --------------------------------------------
extern "C" void kernel_launch(void* const* d_in, const int* in_sizes, int n_in,
                              void* d_out, int out_size) {
    const float* x    = (const float*)d_in[0];
    const void*  ei   = d_in[1];
    const float* W1l  = (const float*)d_in[2];
    const float* W1r  = (const float*)d_in[3];
    const float* att1 = (const float*)d_in[4];
    const float* b1   = (const float*)d_in[5];
    const float* W2l  = (const float*)d_in[6];
    const float* W2r  = (const float*)d_in[7];
    const float* att2 = (const float*)d_in[8];
    const float* b2   = (const float*)d_in[9];
    float* out = (float*)d_out;

    float *XL, *XR, *H1;
    cudaGetSymbolAddress((void**)&XL, g_XL);
    cudaGetSymbolAddress((void**)&XR, g_XR);
    cudaGetSymbolAddress((void**)&H1, g_H1);

    cudaFuncSetAttribute(k_gemm_tc, cudaFuncAttributeMaxDynamicSharedMemorySize,
                         GEMM_SMEM_BYTES);

    // side stream + events (created once, outside graph capture on first call)
    static cudaStream_t s1 = nullptr;
    static cudaEvent_t evFork = nullptr, evG1 = nullptr;
    if (!s1) {
        cudaStreamCreateWithFlags(&s1, cudaStreamNonBlocking);
        cudaEventCreateWithFlags(&evFork, cudaEventDisableTiming);
        cudaEventCreateWithFlags(&evG1, cudaEventDisableTiming);
    }

    int gemm_grid = (N_NODES + 127) / 128;
    int agg_grid  = (N_NODES * 32 + 255) / 256;
    int nblk = (N_NODES + 1023) / 1024;

    // fork: layer-1 GEMM on side stream, concurrent with CSR build
    cudaEventRecord(evFork, 0);
    cudaStreamWaitEvent(s1, evFork, 0);
    k_gemm_tc<<<gemm_grid, 512, GEMM_SMEM_BYTES, s1>>>(x, W1l, W1r, XL, XR, N_NODES);
    cudaEventRecord(evG1, s1);

    // CSR build on main stream (4 kernels)
    k_hist<<<(E_TOT + 255) / 256, 256>>>(ei);
    k_scan1<<<nblk, 1024>>>();
    k_scan3f<<<nblk, 1024>>>(nblk);
    k_scatter<<<(E_TOT + 255) / 256, 256>>>(ei);

    // join
    cudaStreamWaitEvent(0, evG1, 0);

    // layer 1 aggregate
    k_agg<<<agg_grid, 256>>>(XL, XR, att1, b1, H1);

    // layer 2
    k_gemm_tc<<<gemm_grid, 512, GEMM_SMEM_BYTES>>>(H1, W2l, W2r, XL, XR, N_NODES);
    k_agg<<<agg_grid, 256>>>(XL, XR, att2, b2, out);
}

// round 7
// speedup vs baseline: 1.2431x; 1.0488x over previous
#include <cuda_runtime.h>
#include <cuda_fp16.h>
#include <math.h>
#include <stdint.h>

#define N_NODES 50000
#define N_EDGES 1600000
#define E_TOT   (N_EDGES + N_NODES)
#define HID     128
#define SLOPE   0.2f

// ------------------------- device scratch (no allocs allowed) ---------------
__device__ float g_XL[(size_t)N_NODES * HID];
__device__ float g_XR[(size_t)N_NODES * HID];
__device__ float g_H1[(size_t)N_NODES * HID];
__device__ int   g_DEG[N_NODES];        // zero-init; k_scan1 re-zeroes each pass
__device__ int   g_ROWPTR[N_NODES + 1];
__device__ int   g_CURSOR[N_NODES];
__device__ int   g_CSR[E_TOT];
__device__ int   g_PART[64];

// ------------------------- edge dtype helpers --------------------------------
__device__ __forceinline__ int detect_is64(const void* e) {
    int flag = (((const int*)e)[2 * threadIdx.x + 1] != 0);
    return !__syncthreads_or(flag);
}

__device__ __forceinline__ int edge_val(const void* e, int is64, int idx) {
    return is64 ? (int)((const long long*)e)[idx] : ((const int*)e)[idx];
}

// ------------------------- CSR build -----------------------------------------
__global__ __launch_bounds__(256) void k_hist(const void* __restrict__ e) {
    int is64 = detect_is64(e);
    int i = blockIdx.x * 256 + threadIdx.x;
    if (i >= E_TOT) return;
    int d = (i < N_EDGES) ? edge_val(e, is64, N_EDGES + i) : (i - N_EDGES);
    atomicAdd(&g_DEG[d], 1);
}

__global__ __launch_bounds__(1024) void k_scan1() {
    __shared__ int s[1024];
    int i = blockIdx.x * 1024 + threadIdx.x;
    int v = (i < N_NODES) ? g_DEG[i] : 0;
    if (i < N_NODES) g_DEG[i] = 0;          // reset for next launch sequence
    s[threadIdx.x] = v;
    __syncthreads();
    #pragma unroll
    for (int off = 1; off < 1024; off <<= 1) {
        int t = (threadIdx.x >= off) ? s[threadIdx.x - off] : 0;
        __syncthreads();
        s[threadIdx.x] += t;
        __syncthreads();
    }
    if (i < N_NODES) g_ROWPTR[i] = s[threadIdx.x] - v;
    if (threadIdx.x == 1023) g_PART[blockIdx.x] = s[1023];
}

__global__ __launch_bounds__(1024) void k_scan3f(int nblk) {
    __shared__ int off_s;
    if (threadIdx.x < 32) {
        int sum = 0;
        for (int b = threadIdx.x; b < nblk; b += 32)
            sum += (b < (int)blockIdx.x) ? g_PART[b] : 0;
        #pragma unroll
        for (int d = 16; d > 0; d >>= 1)
            sum += __shfl_down_sync(0xFFFFFFFFu, sum, d);
        if (threadIdx.x == 0) off_s = sum;
    }
    __syncthreads();
    int i = blockIdx.x * 1024 + threadIdx.x;
    if (i < N_NODES) {
        int r = g_ROWPTR[i] + off_s;
        g_ROWPTR[i] = r;
        g_CURSOR[i] = r;
    }
    if (i == 0) g_ROWPTR[N_NODES] = E_TOT;
}

__global__ __launch_bounds__(256) void k_scatter(const void* __restrict__ e) {
    int is64 = detect_is64(e);
    int i = blockIdx.x * 256 + threadIdx.x;
    if (i >= E_TOT) return;
    int s_, d_;
    if (i < N_EDGES) {
        s_ = edge_val(e, is64, i);
        d_ = edge_val(e, is64, N_EDGES + i);
    } else {
        s_ = d_ = i - N_EDGES;
    }
    int pos = atomicAdd(&g_CURSOR[d_], 1);
    g_CSR[pos] = s_;
}

// ------------------------- fp16 tensor-core dual GEMM ------------------------
// XL = A @ Wl, XR = A @ Wr as one [M x 256] GEMM, fp32 accumulate.
// mma.sync.aligned.m16n8k16.row.col.f32.f16.f16.f32 (half the HMMA count of
// the tf32 k=8 path; fp16 mantissa == tf32 mantissa -> same accuracy).
// smem: k-pair-packed half2. Asp[row][k/2] stride 20 (banks 20g+t distinct),
// Wsp[k/2][n] stride 260 (banks 4t+g distinct). Static smem: 26.9 KB.
#define ASP_STRIDE 20
#define WSP_STRIDE 260

__device__ __forceinline__ void mma_f16(float4& d, const unsigned a[4], const unsigned b[2]) {
    asm volatile(
        "mma.sync.aligned.m16n8k16.row.col.f32.f16.f16.f32 "
        "{%0,%1,%2,%3}, {%4,%5,%6,%7}, {%8,%9}, {%0,%1,%2,%3};"
        : "+f"(d.x), "+f"(d.y), "+f"(d.z), "+f"(d.w)
        : "r"(a[0]), "r"(a[1]), "r"(a[2]), "r"(a[3]), "r"(b[0]), "r"(b[1]));
}

__global__ __launch_bounds__(512, 1) void k_gemm_tc(const float* __restrict__ A,
                                                    const float* __restrict__ Wl,
                                                    const float* __restrict__ Wr,
                                                    float* __restrict__ XL,
                                                    float* __restrict__ XR, int M) {
    __shared__ __half2 Asp[128][ASP_STRIDE];   // 16 used cols (k-pairs 0..15)
    __shared__ __half2 Wsp[16][WSP_STRIDE];    // 256 used cols

    int tid = threadIdx.x;
    int wid = tid >> 5, lane = tid & 31;
    int g = lane >> 2, t = lane & 3;
    int wm = wid & 3, wn = wid >> 2;
    int m0 = blockIdx.x * 128;

    float4 C[2][8];
    #pragma unroll
    for (int i = 0; i < 2; i++)
        #pragma unroll
        for (int j = 0; j < 8; j++) C[i][j] = make_float4(0.f, 0.f, 0.f, 0.f);

    for (int k0 = 0; k0 < 128; k0 += 32) {
        // A chunk: 128 rows x 32 cols = 1024 float4, 2 per thread
        #pragma unroll
        for (int j = 0; j < 2; j++) {
            int f = tid + 512 * j;
            int row = f >> 3, colf = (f & 7) * 4;   // col multiple of 4
            float4 v = make_float4(0.f, 0.f, 0.f, 0.f);
            if (m0 + row < M)
                v = *(const float4*)(A + (size_t)(m0 + row) * 128 + k0 + colf);
            int c2 = colf >> 1;                     // even pair-col
            Asp[row][c2]     = __floats2half2_rn(v.x, v.y);
            Asp[row][c2 + 1] = __floats2half2_rn(v.z, v.w);
        }
        // W chunk: 16 k-pairs x 64 n-groups = 1024 tasks, 2 per thread
        #pragma unroll
        for (int j = 0; j < 2; j++) {
            int f = tid + 512 * j;
            int k2 = f >> 6, nf = (f & 63) * 4;
            int k = k0 + 2 * k2;
            const float* W0 = (nf < 128) ? (Wl + (size_t)k * 128 + nf)
                                         : (Wr + (size_t)k * 128 + (nf - 128));
            const float* W1 = W0 + 128;             // next k row, same n
            float4 v0 = *(const float4*)W0;
            float4 v1 = *(const float4*)W1;
            Wsp[k2][nf]     = __floats2half2_rn(v0.x, v1.x);
            Wsp[k2][nf + 1] = __floats2half2_rn(v0.y, v1.y);
            Wsp[k2][nf + 2] = __floats2half2_rn(v0.z, v1.z);
            Wsp[k2][nf + 3] = __floats2half2_rn(v0.w, v1.w);
        }
        __syncthreads();

        #pragma unroll
        for (int ks2 = 0; ks2 < 16; ks2 += 8) {     // 2 k-steps of 16
            unsigned a[2][4], b[8][2];
            #pragma unroll
            for (int mt = 0; mt < 2; mt++) {
                int r = wm * 32 + mt * 16;
                a[mt][0] = *(const unsigned*)&Asp[r + g][ks2 + t];
                a[mt][1] = *(const unsigned*)&Asp[r + g + 8][ks2 + t];
                a[mt][2] = *(const unsigned*)&Asp[r + g][ks2 + t + 4];
                a[mt][3] = *(const unsigned*)&Asp[r + g + 8][ks2 + t + 4];
            }
            #pragma unroll
            for (int j = 0; j < 8; j++) {
                int n = wn * 64 + j * 8 + g;
                b[j][0] = *(const unsigned*)&Wsp[ks2 + t][n];
                b[j][1] = *(const unsigned*)&Wsp[ks2 + t + 4][n];
            }
            #pragma unroll
            for (int mt = 0; mt < 2; mt++)
                #pragma unroll
                for (int j = 0; j < 8; j++) mma_f16(C[mt][j], a[mt], b[j]);
        }
        __syncthreads();
    }

    float* base = (wn < 2) ? XL : XR;
    int ncol0 = (wn & 1) * 64;
    #pragma unroll
    for (int mt = 0; mt < 2; mt++) {
        int r0 = m0 + wm * 32 + mt * 16 + g;
        #pragma unroll
        for (int j = 0; j < 8; j++) {
            int c = ncol0 + j * 8 + 2 * t;
            if (r0 < M)
                *(float2*)(base + (size_t)r0 * 128 + c) = make_float2(C[mt][j].x, C[mt][j].y);
            if (r0 + 8 < M)
                *(float2*)(base + (size_t)(r0 + 8) * 128 + c) = make_float2(C[mt][j].z, C[mt][j].w);
        }
    }
}

// ------------------------- GATv2 aggregation (R6 layout, kept) ---------------
__device__ __forceinline__ float logit8(const float4& xA, const float4& xB,
                                        const float4& xrA, const float4& xrB,
                                        const float4& a6A, const float4& a4A,
                                        const float4& a6B, const float4& a4B) {
    float vx = xA.x + xrA.x, vy = xA.y + xrA.y, vz = xA.z + xrA.z, vw = xA.w + xrA.w;
    float p = a6A.x * vx + a4A.x * fabsf(vx);
    p = fmaf(a6A.y, vy, fmaf(a4A.y, fabsf(vy), p));
    p = fmaf(a6A.z, vz, fmaf(a4A.z, fabsf(vz), p));
    p = fmaf(a6A.w, vw, fmaf(a4A.w, fabsf(vw), p));
    vx = xB.x + xrB.x; vy = xB.y + xrB.y; vz = xB.z + xrB.z; vw = xB.w + xrB.w;
    p = fmaf(a6B.x, vx, fmaf(a4B.x, fabsf(vx), p));
    p = fmaf(a6B.y, vy, fmaf(a4B.y, fabsf(vy), p));
    p = fmaf(a6B.z, vz, fmaf(a4B.z, fabsf(vz), p));
    p = fmaf(a6B.w, vw, fmaf(a4B.w, fabsf(vw), p));
    return p;
}

__global__ __launch_bounds__(256) void k_agg(const float* __restrict__ XL,
                                             const float* __restrict__ XR,
                                             const float* __restrict__ att,
                                             const float* __restrict__ bias,
                                             float* __restrict__ out) {
    int warp = (blockIdx.x * blockDim.x + threadIdx.x) >> 5;
    int lane = threadIdx.x & 31;
    if (warp >= N_NODES) return;
    int half = lane >> 4;
    int hl   = lane & 15;

    const float4* attp = (const float4*)att;
    float4 aA = __ldg(attp + 2 * hl), aB = __ldg(attp + 2 * hl + 1);
    float4 a6A = make_float4(0.6f * aA.x, 0.6f * aA.y, 0.6f * aA.z, 0.6f * aA.w);
    float4 a4A = make_float4(0.4f * aA.x, 0.4f * aA.y, 0.4f * aA.z, 0.4f * aA.w);
    float4 a6B = make_float4(0.6f * aB.x, 0.6f * aB.y, 0.6f * aB.z, 0.6f * aB.w);
    float4 a4B = make_float4(0.4f * aB.x, 0.4f * aB.y, 0.4f * aB.z, 0.4f * aB.w);

    const float4* xrp = (const float4*)(XR + (size_t)warp * 128);
    float4 xrA = __ldg(xrp + 2 * hl), xrB = __ldg(xrp + 2 * hl + 1);

    int e0 = __ldg(&g_ROWPTR[warp]);
    int e1 = __ldg(&g_ROWPTR[warp + 1]);

    float s = 0.f;
    float4 accA = make_float4(0.f, 0.f, 0.f, 0.f);
    float4 accB = make_float4(0.f, 0.f, 0.f, 0.f);

    int e = e0;
    for (; e + 4 <= e1; e += 4) {
        int s0 = __ldg(&g_CSR[e + half]);
        int s1 = __ldg(&g_CSR[e + 2 + half]);
        const float4* xp0 = (const float4*)(XL + (size_t)s0 * 128);
        const float4* xp1 = (const float4*)(XL + (size_t)s1 * 128);
        float4 x0A = __ldg(xp0 + 2 * hl), x0B = __ldg(xp0 + 2 * hl + 1);
        float4 x1A = __ldg(xp1 + 2 * hl), x1B = __ldg(xp1 + 2 * hl + 1);

        float p0 = logit8(x0A, x0B, xrA, xrB, a6A, a4A, a6B, a4B);
        float p1 = logit8(x1A, x1B, xrA, xrB, a6A, a4A, a6B, a4B);
        p0 += __shfl_xor_sync(0xFFFFFFFFu, p0, 1);
        p1 += __shfl_xor_sync(0xFFFFFFFFu, p1, 1);
        p0 += __shfl_xor_sync(0xFFFFFFFFu, p0, 2);
        p1 += __shfl_xor_sync(0xFFFFFFFFu, p1, 2);
        float w0 = __expf(p0), w1 = __expf(p1);

        s += w0 + w1;
        accA.x += w0 * x0A.x + w1 * x1A.x;
        accA.y += w0 * x0A.y + w1 * x1A.y;
        accA.z += w0 * x0A.z + w1 * x1A.z;
        accA.w += w0 * x0A.w + w1 * x1A.w;
        accB.x += w0 * x0B.x + w1 * x1B.x;
        accB.y += w0 * x0B.y + w1 * x1B.y;
        accB.z += w0 * x0B.z + w1 * x1B.z;
        accB.w += w0 * x0B.w + w1 * x1B.w;
    }
    for (; e < e1; e += 2) {
        int ei = e + half;
        bool valid = ei < e1;
        int src = __ldg(&g_CSR[valid ? ei : e]);
        const float4* xp = (const float4*)(XL + (size_t)src * 128);
        float4 xA = __ldg(xp + 2 * hl), xB = __ldg(xp + 2 * hl + 1);
        float p = logit8(xA, xB, xrA, xrB, a6A, a4A, a6B, a4B);
        p += __shfl_xor_sync(0xFFFFFFFFu, p, 1);
        p += __shfl_xor_sync(0xFFFFFFFFu, p, 2);
        float w = valid ? __expf(p) : 0.f;
        s += w;
        accA.x += w * xA.x; accA.y += w * xA.y;
        accA.z += w * xA.z; accA.w += w * xA.w;
        accB.x += w * xB.x; accB.y += w * xB.y;
        accB.z += w * xB.z; accB.w += w * xB.w;
    }

    s += __shfl_xor_sync(0xFFFFFFFFu, s, 16);
    accA.x += __shfl_down_sync(0xFFFFFFFFu, accA.x, 16);
    accA.y += __shfl_down_sync(0xFFFFFFFFu, accA.y, 16);
    accA.z += __shfl_down_sync(0xFFFFFFFFu, accA.z, 16);
    accA.w += __shfl_down_sync(0xFFFFFFFFu, accA.w, 16);
    accB.x += __shfl_up_sync(0xFFFFFFFFu, accB.x, 16);
    accB.y += __shfl_up_sync(0xFFFFFFFFu, accB.y, 16);
    accB.z += __shfl_up_sync(0xFFFFFFFFu, accB.z, 16);
    accB.w += __shfl_up_sync(0xFFFFFFFFu, accB.w, 16);

    float inv = 1.f / (s + 1e-16f);
    float4 acc = half ? accB : accA;
    float4 b4 = __ldg((const float4*)bias + 2 * hl + half);
    float4 o;
    o.x = fmaxf(acc.x * inv + b4.x, 0.f);
    o.y = fmaxf(acc.y * inv + b4.y, 0.f);
    o.z = fmaxf(acc.z * inv + b4.z, 0.f);
    o.w = fmaxf(acc.w * inv + b4.w, 0.f);
    *((float4*)(out + (size_t)warp * 128) + 2 * hl + half) = o;
}

// ------------------------- launch --------------------------------------------
extern "C" void kernel_launch(void* const* d_in, const int* in_sizes, int n_in,
                              void* d_out, int out_size) {
    const float* x    = (const float*)d_in[0];
    const void*  ei   = d_in[1];
    const float* W1l  = (const float*)d_in[2];
    const float* W1r  = (const float*)d_in[3];
    const float* att1 = (const float*)d_in[4];
    const float* b1   = (const float*)d_in[5];
    const float* W2l  = (const float*)d_in[6];
    const float* W2r  = (const float*)d_in[7];
    const float* att2 = (const float*)d_in[8];
    const float* b2   = (const float*)d_in[9];
    float* out = (float*)d_out;

    float *XL, *XR, *H1;
    cudaGetSymbolAddress((void**)&XL, g_XL);
    cudaGetSymbolAddress((void**)&XR, g_XR);
    cudaGetSymbolAddress((void**)&H1, g_H1);

    static cudaStream_t s1 = nullptr;
    static cudaEvent_t evFork = nullptr, evG1 = nullptr;
    if (!s1) {
        cudaStreamCreateWithFlags(&s1, cudaStreamNonBlocking);
        cudaEventCreateWithFlags(&evFork, cudaEventDisableTiming);
        cudaEventCreateWithFlags(&evG1, cudaEventDisableTiming);
    }

    int gemm_grid = (N_NODES + 127) / 128;
    int agg_grid  = (N_NODES * 32 + 255) / 256;
    int nblk = (N_NODES + 1023) / 1024;

    // fork: layer-1 GEMM on side stream, concurrent with CSR build
    cudaEventRecord(evFork, 0);
    cudaStreamWaitEvent(s1, evFork, 0);
    k_gemm_tc<<<gemm_grid, 512, 0, s1>>>(x, W1l, W1r, XL, XR, N_NODES);
    cudaEventRecord(evG1, s1);

    // CSR build on main stream
    k_hist<<<(E_TOT + 255) / 256, 256>>>(ei);
    k_scan1<<<nblk, 1024>>>();
    k_scan3f<<<nblk, 1024>>>(nblk);
    k_scatter<<<(E_TOT + 255) / 256, 256>>>(ei);

    // join
    cudaStreamWaitEvent(0, evG1, 0);

    // layer 1 aggregate
    k_agg<<<agg_grid, 256>>>(XL, XR, att1, b1, H1);

    // layer 2
    k_gemm_tc<<<gemm_grid, 512>>>(H1, W2l, W2r, XL, XR, N_NODES);
    k_agg<<<agg_grid, 256>>>(XL, XR, att2, b2, out);
}

// round 8
// speedup vs baseline: 1.2970x; 1.0434x over previous
#include <cuda_runtime.h>
#include <cuda_fp16.h>
#include <math.h>
#include <stdint.h>

#define N_NODES 50000
#define N_EDGES 1600000
#define E_TOT   (N_EDGES + N_NODES)
#define HID     128
#define SLOPE   0.2f

// ------------------------- device scratch (no allocs allowed) ---------------
__device__ __half g_XLh[(size_t)N_NODES * HID];
__device__ __half g_XRh[(size_t)N_NODES * HID];
__device__ float  g_H1[(size_t)N_NODES * HID];
__device__ int    g_DEG[N_NODES];       // zero-init; fused scan re-zeroes
__device__ int    g_ROWPTR[N_NODES + 1];
__device__ int    g_CURSOR[N_NODES];
__device__ int    g_CSR[E_TOT];
__device__ int    g_PART[64];           // zeroed by k_hist block 0 each pass

// ------------------------- edge dtype helpers --------------------------------
__device__ __forceinline__ int detect_is64(const void* e) {
    int flag = (((const int*)e)[2 * threadIdx.x + 1] != 0);
    return !__syncthreads_or(flag);
}

__device__ __forceinline__ int edge_val(const void* e, int is64, int idx) {
    return is64 ? (int)((const long long*)e)[idx] : ((const int*)e)[idx];
}

// ------------------------- CSR build -----------------------------------------
__global__ __launch_bounds__(256) void k_hist(const void* __restrict__ e) {
    if (blockIdx.x == 0 && threadIdx.x < 64) g_PART[threadIdx.x] = 0;
    int is64 = detect_is64(e);
    int i = blockIdx.x * 256 + threadIdx.x;
    if (i >= E_TOT) return;
    int d = (i < N_EDGES) ? edge_val(e, is64, N_EDGES + i) : (i - N_EDGES);
    atomicAdd(&g_DEG[d], 1);
}

// fused scan: block-local scan + decoupled lookback over block partials.
// All 49 blocks are co-resident (49 << 148 SMs); each block's partial is
// >= 848 > 0, so 0 is a safe "not ready" sentinel.
__global__ __launch_bounds__(1024) void k_scanf() {
    __shared__ int s[1024];
    __shared__ int off_s;
    int i = blockIdx.x * 1024 + threadIdx.x;
    int v = (i < N_NODES) ? g_DEG[i] : 0;
    if (i < N_NODES) g_DEG[i] = 0;          // reset for next launch sequence
    s[threadIdx.x] = v;
    __syncthreads();
    #pragma unroll
    for (int off = 1; off < 1024; off <<= 1) {
        int t = (threadIdx.x >= off) ? s[threadIdx.x - off] : 0;
        __syncthreads();
        s[threadIdx.x] += t;
        __syncthreads();
    }
    int incl = s[threadIdx.x];
    if (threadIdx.x == 1023)
        atomicExch(&g_PART[blockIdx.x], incl);   // publish block total
    if (threadIdx.x < 32) {                       // lookback on predecessors
        int sum = 0;
        for (int b = threadIdx.x; b < (int)blockIdx.x; b += 32) {
            int t;
            do { t = atomicAdd(&g_PART[b], 0); } while (t == 0);
            sum += t;
        }
        #pragma unroll
        for (int d = 16; d > 0; d >>= 1)
            sum += __shfl_down_sync(0xFFFFFFFFu, sum, d);
        if (threadIdx.x == 0) off_s = sum;
    }
    __syncthreads();
    if (i < N_NODES) {
        int r = incl - v + off_s;
        g_ROWPTR[i] = r;
        g_CURSOR[i] = r;
    }
    if (i == 0) g_ROWPTR[N_NODES] = E_TOT;
}

__global__ __launch_bounds__(256) void k_scatter(const void* __restrict__ e) {
    int is64 = detect_is64(e);
    int i = blockIdx.x * 256 + threadIdx.x;
    if (i >= E_TOT) return;
    int s_, d_;
    if (i < N_EDGES) {
        s_ = edge_val(e, is64, i);
        d_ = edge_val(e, is64, N_EDGES + i);
    } else {
        s_ = d_ = i - N_EDGES;
    }
    int pos = atomicAdd(&g_CURSOR[d_], 1);
    g_CSR[pos] = s_;
}

// ------------------------- fp16 tensor-core dual GEMM ------------------------
// XL = A @ Wl, XR = A @ Wr as one [M x 256] GEMM, fp32 accumulate, fp16 out.
#define ASP_STRIDE 20
#define WSP_STRIDE 260

__device__ __forceinline__ void mma_f16(float4& d, const unsigned a[4], const unsigned b[2]) {
    asm volatile(
        "mma.sync.aligned.m16n8k16.row.col.f32.f16.f16.f32 "
        "{%0,%1,%2,%3}, {%4,%5,%6,%7}, {%8,%9}, {%0,%1,%2,%3};"
        : "+f"(d.x), "+f"(d.y), "+f"(d.z), "+f"(d.w)
        : "r"(a[0]), "r"(a[1]), "r"(a[2]), "r"(a[3]), "r"(b[0]), "r"(b[1]));
}

__global__ __launch_bounds__(512, 1) void k_gemm_tc(const float* __restrict__ A,
                                                    const float* __restrict__ Wl,
                                                    const float* __restrict__ Wr,
                                                    __half* __restrict__ XL,
                                                    __half* __restrict__ XR, int M) {
    __shared__ __half2 Asp[128][ASP_STRIDE];
    __shared__ __half2 Wsp[16][WSP_STRIDE];

    int tid = threadIdx.x;
    int wid = tid >> 5, lane = tid & 31;
    int g = lane >> 2, t = lane & 3;
    int wm = wid & 3, wn = wid >> 2;
    int m0 = blockIdx.x * 128;

    float4 C[2][8];
    #pragma unroll
    for (int i = 0; i < 2; i++)
        #pragma unroll
        for (int j = 0; j < 8; j++) C[i][j] = make_float4(0.f, 0.f, 0.f, 0.f);

    for (int k0 = 0; k0 < 128; k0 += 32) {
        #pragma unroll
        for (int j = 0; j < 2; j++) {
            int f = tid + 512 * j;
            int row = f >> 3, colf = (f & 7) * 4;
            float4 v = make_float4(0.f, 0.f, 0.f, 0.f);
            if (m0 + row < M)
                v = *(const float4*)(A + (size_t)(m0 + row) * 128 + k0 + colf);
            int c2 = colf >> 1;
            Asp[row][c2]     = __floats2half2_rn(v.x, v.y);
            Asp[row][c2 + 1] = __floats2half2_rn(v.z, v.w);
        }
        #pragma unroll
        for (int j = 0; j < 2; j++) {
            int f = tid + 512 * j;
            int k2 = f >> 6, nf = (f & 63) * 4;
            int k = k0 + 2 * k2;
            const float* W0 = (nf < 128) ? (Wl + (size_t)k * 128 + nf)
                                         : (Wr + (size_t)k * 128 + (nf - 128));
            const float* W1 = W0 + 128;
            float4 v0 = *(const float4*)W0;
            float4 v1 = *(const float4*)W1;
            Wsp[k2][nf]     = __floats2half2_rn(v0.x, v1.x);
            Wsp[k2][nf + 1] = __floats2half2_rn(v0.y, v1.y);
            Wsp[k2][nf + 2] = __floats2half2_rn(v0.z, v1.z);
            Wsp[k2][nf + 3] = __floats2half2_rn(v0.w, v1.w);
        }
        __syncthreads();

        #pragma unroll
        for (int ks2 = 0; ks2 < 16; ks2 += 8) {
            unsigned a[2][4], b[8][2];
            #pragma unroll
            for (int mt = 0; mt < 2; mt++) {
                int r = wm * 32 + mt * 16;
                a[mt][0] = *(const unsigned*)&Asp[r + g][ks2 + t];
                a[mt][1] = *(const unsigned*)&Asp[r + g + 8][ks2 + t];
                a[mt][2] = *(const unsigned*)&Asp[r + g][ks2 + t + 4];
                a[mt][3] = *(const unsigned*)&Asp[r + g + 8][ks2 + t + 4];
            }
            #pragma unroll
            for (int j = 0; j < 8; j++) {
                int n = wn * 64 + j * 8 + g;
                b[j][0] = *(const unsigned*)&Wsp[ks2 + t][n];
                b[j][1] = *(const unsigned*)&Wsp[ks2 + t + 4][n];
            }
            #pragma unroll
            for (int mt = 0; mt < 2; mt++)
                #pragma unroll
                for (int j = 0; j < 8; j++) mma_f16(C[mt][j], a[mt], b[j]);
        }
        __syncthreads();
    }

    __half* base = (wn < 2) ? XL : XR;
    int ncol0 = (wn & 1) * 64;
    #pragma unroll
    for (int mt = 0; mt < 2; mt++) {
        int r0 = m0 + wm * 32 + mt * 16 + g;
        #pragma unroll
        for (int j = 0; j < 8; j++) {
            int c = ncol0 + j * 8 + 2 * t;
            if (r0 < M)
                *(__half2*)(base + (size_t)r0 * 128 + c) = __floats2half2_rn(C[mt][j].x, C[mt][j].y);
            if (r0 + 8 < M)
                *(__half2*)(base + (size_t)(r0 + 8) * 128 + c) = __floats2half2_rn(C[mt][j].z, C[mt][j].w);
        }
    }
}

// ------------------------- GATv2 aggregation ---------------------------------
// Warp per dst node, two edges in flight (lanes 0-15 even edge, 16-31 odd).
// fp16 rows: lane loads ONE uint4 (16 B = its 8 channels) -> 1 LDG.128/edge,
// 2 lines/edge. Converts to fp32 for logit+accumulate (math identical to R6).
__device__ __forceinline__ void unp16(uint4 u, float4& A, float4& B) {
    float2 f0 = __half22float2(*reinterpret_cast<__half2*>(&u.x));
    float2 f1 = __half22float2(*reinterpret_cast<__half2*>(&u.y));
    float2 f2 = __half22float2(*reinterpret_cast<__half2*>(&u.z));
    float2 f3 = __half22float2(*reinterpret_cast<__half2*>(&u.w));
    A = make_float4(f0.x, f0.y, f1.x, f1.y);
    B = make_float4(f2.x, f2.y, f3.x, f3.y);
}

__device__ __forceinline__ float logit8(const float4& xA, const float4& xB,
                                        const float4& xrA, const float4& xrB,
                                        const float4& a6A, const float4& a4A,
                                        const float4& a6B, const float4& a4B) {
    float vx = xA.x + xrA.x, vy = xA.y + xrA.y, vz = xA.z + xrA.z, vw = xA.w + xrA.w;
    float p = a6A.x * vx + a4A.x * fabsf(vx);
    p = fmaf(a6A.y, vy, fmaf(a4A.y, fabsf(vy), p));
    p = fmaf(a6A.z, vz, fmaf(a4A.z, fabsf(vz), p));
    p = fmaf(a6A.w, vw, fmaf(a4A.w, fabsf(vw), p));
    vx = xB.x + xrB.x; vy = xB.y + xrB.y; vz = xB.z + xrB.z; vw = xB.w + xrB.w;
    p = fmaf(a6B.x, vx, fmaf(a4B.x, fabsf(vx), p));
    p = fmaf(a6B.y, vy, fmaf(a4B.y, fabsf(vy), p));
    p = fmaf(a6B.z, vz, fmaf(a4B.z, fabsf(vz), p));
    p = fmaf(a6B.w, vw, fmaf(a4B.w, fabsf(vw), p));
    return p;
}

__global__ __launch_bounds__(256) void k_agg(const __half* __restrict__ XL,
                                             const __half* __restrict__ XR,
                                             const float* __restrict__ att,
                                             const float* __restrict__ bias,
                                             float* __restrict__ out) {
    int warp = (blockIdx.x * blockDim.x + threadIdx.x) >> 5;
    int lane = threadIdx.x & 31;
    if (warp >= N_NODES) return;
    int half = lane >> 4;
    int hl   = lane & 15;

    const float4* attp = (const float4*)att;
    float4 aA = __ldg(attp + 2 * hl), aB = __ldg(attp + 2 * hl + 1);
    float4 a6A = make_float4(0.6f * aA.x, 0.6f * aA.y, 0.6f * aA.z, 0.6f * aA.w);
    float4 a4A = make_float4(0.4f * aA.x, 0.4f * aA.y, 0.4f * aA.z, 0.4f * aA.w);
    float4 a6B = make_float4(0.6f * aB.x, 0.6f * aB.y, 0.6f * aB.z, 0.6f * aB.w);
    float4 a4B = make_float4(0.4f * aB.x, 0.4f * aB.y, 0.4f * aB.z, 0.4f * aB.w);

    uint4 xru = __ldg((const uint4*)(XR + (size_t)warp * 128) + hl);
    float4 xrA, xrB;
    unp16(xru, xrA, xrB);

    int e0 = __ldg(&g_ROWPTR[warp]);
    int e1 = __ldg(&g_ROWPTR[warp + 1]);

    float s = 0.f;
    float4 accA = make_float4(0.f, 0.f, 0.f, 0.f);
    float4 accB = make_float4(0.f, 0.f, 0.f, 0.f);

    int e = e0;
    for (; e + 4 <= e1; e += 4) {
        int s0 = __ldg(&g_CSR[e + half]);
        int s1 = __ldg(&g_CSR[e + 2 + half]);
        uint4 u0 = __ldg((const uint4*)(XL + (size_t)s0 * 128) + hl);
        uint4 u1 = __ldg((const uint4*)(XL + (size_t)s1 * 128) + hl);
        float4 x0A, x0B, x1A, x1B;
        unp16(u0, x0A, x0B);
        unp16(u1, x1A, x1B);

        float p0 = logit8(x0A, x0B, xrA, xrB, a6A, a4A, a6B, a4B);
        float p1 = logit8(x1A, x1B, xrA, xrB, a6A, a4A, a6B, a4B);
        p0 += __shfl_xor_sync(0xFFFFFFFFu, p0, 1);
        p1 += __shfl_xor_sync(0xFFFFFFFFu, p1, 1);
        p0 += __shfl_xor_sync(0xFFFFFFFFu, p0, 2);
        p1 += __shfl_xor_sync(0xFFFFFFFFu, p1, 2);
        float w0 = __expf(p0), w1 = __expf(p1);

        s += w0 + w1;
        accA.x += w0 * x0A.x + w1 * x1A.x;
        accA.y += w0 * x0A.y + w1 * x1A.y;
        accA.z += w0 * x0A.z + w1 * x1A.z;
        accA.w += w0 * x0A.w + w1 * x1A.w;
        accB.x += w0 * x0B.x + w1 * x1B.x;
        accB.y += w0 * x0B.y + w1 * x1B.y;
        accB.z += w0 * x0B.z + w1 * x1B.z;
        accB.w += w0 * x0B.w + w1 * x1B.w;
    }
    for (; e < e1; e += 2) {
        int ei = e + half;
        bool valid = ei < e1;
        int src = __ldg(&g_CSR[valid ? ei : e]);
        uint4 u = __ldg((const uint4*)(XL + (size_t)src * 128) + hl);
        float4 xA, xB;
        unp16(u, xA, xB);
        float p = logit8(xA, xB, xrA, xrB, a6A, a4A, a6B, a4B);
        p += __shfl_xor_sync(0xFFFFFFFFu, p, 1);
        p += __shfl_xor_sync(0xFFFFFFFFu, p, 2);
        float w = valid ? __expf(p) : 0.f;
        s += w;
        accA.x += w * xA.x; accA.y += w * xA.y;
        accA.z += w * xA.z; accA.w += w * xA.w;
        accB.x += w * xB.x; accB.y += w * xB.y;
        accB.z += w * xB.z; accB.w += w * xB.w;
    }

    s += __shfl_xor_sync(0xFFFFFFFFu, s, 16);
    accA.x += __shfl_down_sync(0xFFFFFFFFu, accA.x, 16);
    accA.y += __shfl_down_sync(0xFFFFFFFFu, accA.y, 16);
    accA.z += __shfl_down_sync(0xFFFFFFFFu, accA.z, 16);
    accA.w += __shfl_down_sync(0xFFFFFFFFu, accA.w, 16);
    accB.x += __shfl_up_sync(0xFFFFFFFFu, accB.x, 16);
    accB.y += __shfl_up_sync(0xFFFFFFFFu, accB.y, 16);
    accB.z += __shfl_up_sync(0xFFFFFFFFu, accB.z, 16);
    accB.w += __shfl_up_sync(0xFFFFFFFFu, accB.w, 16);

    float inv = 1.f / (s + 1e-16f);
    float4 acc = half ? accB : accA;
    float4 b4 = __ldg((const float4*)bias + 2 * hl + half);
    float4 o;
    o.x = fmaxf(acc.x * inv + b4.x, 0.f);
    o.y = fmaxf(acc.y * inv + b4.y, 0.f);
    o.z = fmaxf(acc.z * inv + b4.z, 0.f);
    o.w = fmaxf(acc.w * inv + b4.w, 0.f);
    *((float4*)(out + (size_t)warp * 128) + 2 * hl + half) = o;
}

// ------------------------- launch --------------------------------------------
extern "C" void kernel_launch(void* const* d_in, const int* in_sizes, int n_in,
                              void* d_out, int out_size) {
    const float* x    = (const float*)d_in[0];
    const void*  ei   = d_in[1];
    const float* W1l  = (const float*)d_in[2];
    const float* W1r  = (const float*)d_in[3];
    const float* att1 = (const float*)d_in[4];
    const float* b1   = (const float*)d_in[5];
    const float* W2l  = (const float*)d_in[6];
    const float* W2r  = (const float*)d_in[7];
    const float* att2 = (const float*)d_in[8];
    const float* b2   = (const float*)d_in[9];
    float* out = (float*)d_out;

    __half *XL, *XR;
    float *H1;
    cudaGetSymbolAddress((void**)&XL, g_XLh);
    cudaGetSymbolAddress((void**)&XR, g_XRh);
    cudaGetSymbolAddress((void**)&H1, g_H1);

    static cudaStream_t s1 = nullptr;
    static cudaEvent_t evFork = nullptr, evG1 = nullptr;
    if (!s1) {
        cudaStreamCreateWithFlags(&s1, cudaStreamNonBlocking);
        cudaEventCreateWithFlags(&evFork, cudaEventDisableTiming);
        cudaEventCreateWithFlags(&evG1, cudaEventDisableTiming);
    }

    int gemm_grid = (N_NODES + 127) / 128;
    int agg_grid  = (N_NODES * 32 + 255) / 256;
    int nblk = (N_NODES + 1023) / 1024;

    // fork: layer-1 GEMM on side stream, concurrent with CSR build
    cudaEventRecord(evFork, 0);
    cudaStreamWaitEvent(s1, evFork, 0);
    k_gemm_tc<<<gemm_grid, 512, 0, s1>>>(x, W1l, W1r, XL, XR, N_NODES);
    cudaEventRecord(evG1, s1);

    // CSR build on main stream (3 kernels)
    k_hist<<<(E_TOT + 255) / 256, 256>>>(ei);
    k_scanf<<<nblk, 1024>>>();
    k_scatter<<<(E_TOT + 255) / 256, 256>>>(ei);

    // join
    cudaStreamWaitEvent(0, evG1, 0);

    // layer 1 aggregate
    k_agg<<<agg_grid, 256>>>(XL, XR, att1, b1, H1);

    // layer 2
    k_gemm_tc<<<gemm_grid, 512>>>(H1, W2l, W2r, XL, XR, N_NODES);
    k_agg<<<agg_grid, 256>>>(XL, XR, att2, b2, out);
}